// round 1
// baseline (speedup 1.0000x reference)
#include <cuda_runtime.h>
#include <math.h>

#define SEQ 2048
#define DM 1024
#define NH 16
#define HD 64
#define NB 2
#define MROWS (NB * SEQ)   // 4096

// Scratch buffers (allocation-free rule: __device__ globals)
__device__ float g_qw[MROWS * DM];
__device__ float g_kw[MROWS * DM];
__device__ float g_vw[MROWS * DM];
__device__ float g_ctx[MROWS * DM];

// ---------------------------------------------------------------------------
// Classic 128x128x8 register-tiled SGEMM with bias:  C = A(MxK) * B(KxN) + bias
// 256 threads, 8x8 accumulators per thread, A stored transposed in smem.
// ---------------------------------------------------------------------------
__global__ __launch_bounds__(256) void sgemm_bias(
    const float* __restrict__ A, const float* __restrict__ B,
    const float* __restrict__ bias, float* __restrict__ C,
    int M, int N, int K)
{
    __shared__ float As[8][132];   // [k][m], padded
    __shared__ float Bs[8][132];   // [k][n], padded

    const int tid = threadIdx.x;
    const int tx = tid & 15;        // 0..15 -> 128 cols via 2 groups of 4
    const int ty = tid >> 4;        // 0..15 -> 128 rows via 2 groups of 4
    const int bm = blockIdx.y * 128;
    const int bn = blockIdx.x * 128;

    const int arow = tid >> 1;          // 0..127
    const int acol = (tid & 1) * 4;     // 0 or 4
    const int brow = tid >> 5;          // 0..7
    const int bcol = (tid & 31) * 4;    // 0..124

    const float* Aptr = A + (size_t)(bm + arow) * K + acol;
    const float* Bptr = B + (size_t)brow * N + bn + bcol;

    float c[8][8];
#pragma unroll
    for (int i = 0; i < 8; i++)
#pragma unroll
        for (int j = 0; j < 8; j++) c[i][j] = 0.0f;

    for (int k0 = 0; k0 < K; k0 += 8) {
        float4 av = *(const float4*)(Aptr + k0);
        float4 bv = *(const float4*)(Bptr + (size_t)k0 * N);
        As[acol + 0][arow] = av.x;
        As[acol + 1][arow] = av.y;
        As[acol + 2][arow] = av.z;
        As[acol + 3][arow] = av.w;
        *(float4*)&Bs[brow][bcol] = bv;
        __syncthreads();

#pragma unroll
        for (int k = 0; k < 8; k++) {
            float a[8], b[8];
            float4 a0 = *(const float4*)&As[k][ty * 4];
            float4 a1 = *(const float4*)&As[k][64 + ty * 4];
            float4 b0 = *(const float4*)&Bs[k][tx * 4];
            float4 b1 = *(const float4*)&Bs[k][64 + tx * 4];
            a[0] = a0.x; a[1] = a0.y; a[2] = a0.z; a[3] = a0.w;
            a[4] = a1.x; a[5] = a1.y; a[6] = a1.z; a[7] = a1.w;
            b[0] = b0.x; b[1] = b0.y; b[2] = b0.z; b[3] = b0.w;
            b[4] = b1.x; b[5] = b1.y; b[6] = b1.z; b[7] = b1.w;
#pragma unroll
            for (int i = 0; i < 8; i++)
#pragma unroll
                for (int j = 0; j < 8; j++)
                    c[i][j] = fmaf(a[i], b[j], c[i][j]);
        }
        __syncthreads();
    }

#pragma unroll
    for (int ih = 0; ih < 2; ih++)
#pragma unroll
        for (int ii = 0; ii < 4; ii++) {
            int r = bm + ih * 64 + ty * 4 + ii;
#pragma unroll
            for (int jh = 0; jh < 2; jh++) {
                int cb = bn + jh * 64 + tx * 4;
                float4 v;
                v.x = c[ih * 4 + ii][jh * 4 + 0] + bias[cb + 0];
                v.y = c[ih * 4 + ii][jh * 4 + 1] + bias[cb + 1];
                v.z = c[ih * 4 + ii][jh * 4 + 2] + bias[cb + 2];
                v.w = c[ih * 4 + ii][jh * 4 + 3] + bias[cb + 3];
                *(float4*)&C[(size_t)r * N + cb] = v;
            }
        }
}

// ---------------------------------------------------------------------------
// Fused flash-attention: one block per (query-tile of 64, head, batch).
// 128 threads. Key tiles of 32. Online softmax, masking identical to ref:
// s -= (1-m)*1e12, then softmax — the alpha rescale wipes all-masked prefixes.
// ---------------------------------------------------------------------------
#define QS_STRIDE 68   // [d][row] transposed, padded
#define KS_STRIDE 36   // [d][key] transposed, padded
#define VS_STRIDE 68   // [key][d] natural, padded
#define PS_STRIDE 36   // [row][key] natural, padded

__global__ __launch_bounds__(128) void attn_kernel(
    const float* __restrict__ qw, const float* __restrict__ kw,
    const float* __restrict__ vw, const int* __restrict__ vmask,
    float* __restrict__ ctx)
{
    __shared__ float Qs[64 * QS_STRIDE];
    __shared__ float KV[64 * KS_STRIDE];   // 2304 floats: K(64x36) union V(32x68=2176)
    __shared__ float Ps[64 * PS_STRIDE];
    __shared__ float Ms[32];

    const int tid = threadIdx.x;
    const int tx = tid & 7;    // 0..7
    const int ty = tid >> 3;   // 0..15
    const int qt = blockIdx.x;
    const int h  = blockIdx.y;
    const int b  = blockIdx.z;

    // Load Q tile (64 queries x 64 dims), transposed + pre-scaled by 1/sqrt(64)
    const float* qbase = qw + ((size_t)b * SEQ + qt * 64) * DM + h * HD;
    for (int i = tid; i < 64 * 64; i += 128) {
        int r = i >> 6, d = i & 63;
        Qs[d * QS_STRIDE + r] = qbase[(size_t)r * DM + d] * 0.125f;
    }

    float m[4], l[4], o[4][8];
#pragma unroll
    for (int ii = 0; ii < 4; ii++) {
        m[ii] = -1e30f; l[ii] = 0.0f;
#pragma unroll
        for (int ee = 0; ee < 8; ee++) o[ii][ee] = 0.0f;
    }

    for (int kt = 0; kt < SEQ / 32; kt++) {
        __syncthreads();   // previous PV done reading KV union
        // Load K tile (32 keys x 64 dims), transposed
        const float* kbase = kw + ((size_t)b * SEQ + kt * 32) * DM + h * HD;
        for (int i = tid; i < 32 * 64; i += 128) {
            int j = i >> 6, d = i & 63;
            KV[d * KS_STRIDE + j] = kbase[(size_t)j * DM + d];
        }
        if (tid < 32) Ms[tid] = (float)vmask[b * SEQ + kt * 32 + tid];
        __syncthreads();

        // S = (Q/8) . K^T   (64x32, each thread 4 rows x 4 cols)
        float s[4][4];
#pragma unroll
        for (int ii = 0; ii < 4; ii++)
#pragma unroll
            for (int jj = 0; jj < 4; jj++) s[ii][jj] = 0.0f;

#pragma unroll 16
        for (int d = 0; d < 64; d++) {
            float4 qv = *(const float4*)&Qs[d * QS_STRIDE + ty * 4];
            float4 kv = *(const float4*)&KV[d * KS_STRIDE + tx * 4];
            float qa[4] = {qv.x, qv.y, qv.z, qv.w};
            float kb[4] = {kv.x, kv.y, kv.z, kv.w};
#pragma unroll
            for (int ii = 0; ii < 4; ii++)
#pragma unroll
                for (int jj = 0; jj < 4; jj++)
                    s[ii][jj] = fmaf(qa[ii], kb[jj], s[ii][jj]);
        }

        // Mask + online softmax (row groups of 8 lanes share a query row set)
#pragma unroll
        for (int ii = 0; ii < 4; ii++) {
            float mx = -1e30f;
#pragma unroll
            for (int jj = 0; jj < 4; jj++) {
                s[ii][jj] -= (1.0f - Ms[tx * 4 + jj]) * 1e12f;
                mx = fmaxf(mx, s[ii][jj]);
            }
            mx = fmaxf(mx, __shfl_xor_sync(0xffffffffu, mx, 1, 8));
            mx = fmaxf(mx, __shfl_xor_sync(0xffffffffu, mx, 2, 8));
            mx = fmaxf(mx, __shfl_xor_sync(0xffffffffu, mx, 4, 8));
            float mnew = fmaxf(m[ii], mx);
            float alpha = __expf(m[ii] - mnew);
            float p[4];
            float sum = 0.0f;
#pragma unroll
            for (int jj = 0; jj < 4; jj++) {
                p[jj] = __expf(s[ii][jj] - mnew);
                sum += p[jj];
            }
            sum += __shfl_xor_sync(0xffffffffu, sum, 1, 8);
            sum += __shfl_xor_sync(0xffffffffu, sum, 2, 8);
            sum += __shfl_xor_sync(0xffffffffu, sum, 4, 8);
            l[ii] = l[ii] * alpha + sum;
            m[ii] = mnew;
#pragma unroll
            for (int ee = 0; ee < 8; ee++) o[ii][ee] *= alpha;
            *(float4*)&Ps[(ty * 4 + ii) * PS_STRIDE + tx * 4] =
                make_float4(p[0], p[1], p[2], p[3]);
        }
        __syncthreads();   // Ps written; all done reading K from KV union

        // Load V tile (32 keys x 64 dims), natural layout, into KV union
        const float* vbase = vw + ((size_t)b * SEQ + kt * 32) * DM + h * HD;
        for (int i = tid; i < 32 * 64; i += 128) {
            int j = i >> 6, d = i & 63;
            KV[j * VS_STRIDE + d] = vbase[(size_t)j * DM + d];
        }
        __syncthreads();

        // O += P . V   (each thread 4 rows x 8 dim-cols)
#pragma unroll 8
        for (int j = 0; j < 32; j++) {
            float4 v0 = *(const float4*)&KV[j * VS_STRIDE + tx * 8];
            float4 v1 = *(const float4*)&KV[j * VS_STRIDE + tx * 8 + 4];
            float vv[8] = {v0.x, v0.y, v0.z, v0.w, v1.x, v1.y, v1.z, v1.w};
            float pp[4];
#pragma unroll
            for (int ii = 0; ii < 4; ii++)
                pp[ii] = Ps[(ty * 4 + ii) * PS_STRIDE + j];
#pragma unroll
            for (int ii = 0; ii < 4; ii++)
#pragma unroll
                for (int ee = 0; ee < 8; ee++)
                    o[ii][ee] = fmaf(pp[ii], vv[ee], o[ii][ee]);
        }
    }

    // Normalize and write ctx[b, q, h*64 + e]
    float* obase = ctx + ((size_t)b * SEQ + qt * 64) * DM + h * HD;
#pragma unroll
    for (int ii = 0; ii < 4; ii++) {
        float inv = 1.0f / l[ii];
        float4 w0, w1;
        w0.x = o[ii][0] * inv; w0.y = o[ii][1] * inv;
        w0.z = o[ii][2] * inv; w0.w = o[ii][3] * inv;
        w1.x = o[ii][4] * inv; w1.y = o[ii][5] * inv;
        w1.z = o[ii][6] * inv; w1.w = o[ii][7] * inv;
        size_t row = (size_t)(ty * 4 + ii) * DM + tx * 8;
        *(float4*)&obase[row]     = w0;
        *(float4*)&obase[row + 4] = w1;
    }
}

// ---------------------------------------------------------------------------
extern "C" void kernel_launch(void* const* d_in, const int* in_sizes, int n_in,
                              void* d_out, int out_size)
{
    const float* q    = (const float*)d_in[0];
    const float* k    = (const float*)d_in[1];
    const float* v    = (const float*)d_in[2];
    const int*   mask = (const int*)  d_in[3];
    const float* Wq   = (const float*)d_in[4];
    const float* bq   = (const float*)d_in[5];
    const float* Wk   = (const float*)d_in[6];
    const float* bk   = (const float*)d_in[7];
    const float* Wv   = (const float*)d_in[8];
    const float* bv   = (const float*)d_in[9];
    const float* Wo   = (const float*)d_in[10];
    const float* bo   = (const float*)d_in[11];
    float* out = (float*)d_out;

    void *pqw, *pkw, *pvw, *pctx;
    cudaGetSymbolAddress(&pqw, g_qw);
    cudaGetSymbolAddress(&pkw, g_kw);
    cudaGetSymbolAddress(&pvw, g_vw);
    cudaGetSymbolAddress(&pctx, g_ctx);

    dim3 ggrid(DM / 128, MROWS / 128);   // (8, 32)

    sgemm_bias<<<ggrid, 256>>>(q, Wq, bq, (float*)pqw, MROWS, DM, DM);
    sgemm_bias<<<ggrid, 256>>>(k, Wk, bk, (float*)pkw, MROWS, DM, DM);
    sgemm_bias<<<ggrid, 256>>>(v, Wv, bv, (float*)pvw, MROWS, DM, DM);

    attn_kernel<<<dim3(SEQ / 64, NH, NB), 128>>>(
        (const float*)pqw, (const float*)pkw, (const float*)pvw, mask,
        (float*)pctx);

    sgemm_bias<<<ggrid, 256>>>((const float*)pctx, Wo, bo, out, MROWS, DM, DM);
}

// round 2
// speedup vs baseline: 1.0023x; 1.0023x over previous
#include <cuda_runtime.h>
#include <math.h>

#define SEQ 2048
#define DM 1024
#define NH 16
#define HD 64
#define NB 2
#define MROWS (NB * SEQ)   // 4096

// Scratch buffers (allocation-free rule: __device__ globals)
__device__ float g_qw[MROWS * DM];
__device__ float g_kw[MROWS * DM];
__device__ float g_vw[MROWS * DM];
__device__ float g_ctx[MROWS * DM];

// ---------------------------------------------------------------------------
// Classic 128x128x8 register-tiled SGEMM with bias:  C = A(MxK) * B(KxN) + bias
// 256 threads, 8x8 accumulators per thread, A stored transposed in smem.
// ---------------------------------------------------------------------------
__global__ __launch_bounds__(256) void sgemm_bias(
    const float* __restrict__ A, const float* __restrict__ B,
    const float* __restrict__ bias, float* __restrict__ C,
    int M, int N, int K)
{
    __shared__ float As[8][132];   // [k][m], padded
    __shared__ float Bs[8][132];   // [k][n], padded

    const int tid = threadIdx.x;
    const int tx = tid & 15;        // 0..15 -> 128 cols via 2 groups of 4
    const int ty = tid >> 4;        // 0..15 -> 128 rows via 2 groups of 4
    const int bm = blockIdx.y * 128;
    const int bn = blockIdx.x * 128;

    const int arow = tid >> 1;          // 0..127
    const int acol = (tid & 1) * 4;     // 0 or 4
    const int brow = tid >> 5;          // 0..7
    const int bcol = (tid & 31) * 4;    // 0..124

    const float* Aptr = A + (size_t)(bm + arow) * K + acol;
    const float* Bptr = B + (size_t)brow * N + bn + bcol;

    float c[8][8];
#pragma unroll
    for (int i = 0; i < 8; i++)
#pragma unroll
        for (int j = 0; j < 8; j++) c[i][j] = 0.0f;

    for (int k0 = 0; k0 < K; k0 += 8) {
        float4 av = *(const float4*)(Aptr + k0);
        float4 bv = *(const float4*)(Bptr + (size_t)k0 * N);
        As[acol + 0][arow] = av.x;
        As[acol + 1][arow] = av.y;
        As[acol + 2][arow] = av.z;
        As[acol + 3][arow] = av.w;
        *(float4*)&Bs[brow][bcol] = bv;
        __syncthreads();

#pragma unroll
        for (int k = 0; k < 8; k++) {
            float a[8], b[8];
            float4 a0 = *(const float4*)&As[k][ty * 4];
            float4 a1 = *(const float4*)&As[k][64 + ty * 4];
            float4 b0 = *(const float4*)&Bs[k][tx * 4];
            float4 b1 = *(const float4*)&Bs[k][64 + tx * 4];
            a[0] = a0.x; a[1] = a0.y; a[2] = a0.z; a[3] = a0.w;
            a[4] = a1.x; a[5] = a1.y; a[6] = a1.z; a[7] = a1.w;
            b[0] = b0.x; b[1] = b0.y; b[2] = b0.z; b[3] = b0.w;
            b[4] = b1.x; b[5] = b1.y; b[6] = b1.z; b[7] = b1.w;
#pragma unroll
            for (int i = 0; i < 8; i++)
#pragma unroll
                for (int j = 0; j < 8; j++)
                    c[i][j] = fmaf(a[i], b[j], c[i][j]);
        }
        __syncthreads();
    }

#pragma unroll
    for (int ih = 0; ih < 2; ih++)
#pragma unroll
        for (int ii = 0; ii < 4; ii++) {
            int r = bm + ih * 64 + ty * 4 + ii;
#pragma unroll
            for (int jh = 0; jh < 2; jh++) {
                int cb = bn + jh * 64 + tx * 4;
                float4 v;
                v.x = c[ih * 4 + ii][jh * 4 + 0] + bias[cb + 0];
                v.y = c[ih * 4 + ii][jh * 4 + 1] + bias[cb + 1];
                v.z = c[ih * 4 + ii][jh * 4 + 2] + bias[cb + 2];
                v.w = c[ih * 4 + ii][jh * 4 + 3] + bias[cb + 3];
                *(float4*)&C[(size_t)r * N + cb] = v;
            }
        }
}

// ---------------------------------------------------------------------------
// Fused flash-attention: one block per (query-tile of 64, head, batch).
// 128 threads. Key tiles of 32. Online softmax, masking identical to ref:
// s -= (1-m)*1e12, then softmax — the alpha rescale wipes all-masked prefixes.
// ---------------------------------------------------------------------------
#define QS_STRIDE 68   // [d][row] transposed, padded
#define KS_STRIDE 36   // [d][key] transposed, padded
#define VS_STRIDE 68   // [key][d] natural, padded
#define PS_STRIDE 36   // [row][key] natural, padded

__global__ __launch_bounds__(128) void attn_kernel(
    const float* __restrict__ qw, const float* __restrict__ kw,
    const float* __restrict__ vw, const int* __restrict__ vmask,
    float* __restrict__ ctx)
{
    __shared__ float Qs[64 * QS_STRIDE];
    __shared__ float KV[64 * KS_STRIDE];   // 2304 floats: K(64x36) union V(32x68=2176)
    __shared__ float Ps[64 * PS_STRIDE];
    __shared__ float Ms[32];

    const int tid = threadIdx.x;
    const int tx = tid & 7;    // 0..7
    const int ty = tid >> 3;   // 0..15
    const int qt = blockIdx.x;
    const int h  = blockIdx.y;
    const int b  = blockIdx.z;

    // Load Q tile (64 queries x 64 dims), transposed + pre-scaled by 1/sqrt(64)
    const float* qbase = qw + ((size_t)b * SEQ + qt * 64) * DM + h * HD;
    for (int i = tid; i < 64 * 64; i += 128) {
        int r = i >> 6, d = i & 63;
        Qs[d * QS_STRIDE + r] = qbase[(size_t)r * DM + d] * 0.125f;
    }

    float m[4], l[4], o[4][8];
#pragma unroll
    for (int ii = 0; ii < 4; ii++) {
        m[ii] = -1e30f; l[ii] = 0.0f;
#pragma unroll
        for (int ee = 0; ee < 8; ee++) o[ii][ee] = 0.0f;
    }

    for (int kt = 0; kt < SEQ / 32; kt++) {
        __syncthreads();   // previous PV done reading KV union
        // Load K tile (32 keys x 64 dims), transposed
        const float* kbase = kw + ((size_t)b * SEQ + kt * 32) * DM + h * HD;
        for (int i = tid; i < 32 * 64; i += 128) {
            int j = i >> 6, d = i & 63;
            KV[d * KS_STRIDE + j] = kbase[(size_t)j * DM + d];
        }
        if (tid < 32) Ms[tid] = (float)vmask[b * SEQ + kt * 32 + tid];
        __syncthreads();

        // S = (Q/8) . K^T   (64x32, each thread 4 rows x 4 cols)
        float s[4][4];
#pragma unroll
        for (int ii = 0; ii < 4; ii++)
#pragma unroll
            for (int jj = 0; jj < 4; jj++) s[ii][jj] = 0.0f;

#pragma unroll 16
        for (int d = 0; d < 64; d++) {
            float4 qv = *(const float4*)&Qs[d * QS_STRIDE + ty * 4];
            float4 kv = *(const float4*)&KV[d * KS_STRIDE + tx * 4];
            float qa[4] = {qv.x, qv.y, qv.z, qv.w};
            float kb[4] = {kv.x, kv.y, kv.z, kv.w};
#pragma unroll
            for (int ii = 0; ii < 4; ii++)
#pragma unroll
                for (int jj = 0; jj < 4; jj++)
                    s[ii][jj] = fmaf(qa[ii], kb[jj], s[ii][jj]);
        }

        // Mask + online softmax (row groups of 8 lanes share a query row set)
#pragma unroll
        for (int ii = 0; ii < 4; ii++) {
            float mx = -1e30f;
#pragma unroll
            for (int jj = 0; jj < 4; jj++) {
                s[ii][jj] -= (1.0f - Ms[tx * 4 + jj]) * 1e12f;
                mx = fmaxf(mx, s[ii][jj]);
            }
            mx = fmaxf(mx, __shfl_xor_sync(0xffffffffu, mx, 1, 8));
            mx = fmaxf(mx, __shfl_xor_sync(0xffffffffu, mx, 2, 8));
            mx = fmaxf(mx, __shfl_xor_sync(0xffffffffu, mx, 4, 8));
            float mnew = fmaxf(m[ii], mx);
            float alpha = __expf(m[ii] - mnew);
            float p[4];
            float sum = 0.0f;
#pragma unroll
            for (int jj = 0; jj < 4; jj++) {
                p[jj] = __expf(s[ii][jj] - mnew);
                sum += p[jj];
            }
            sum += __shfl_xor_sync(0xffffffffu, sum, 1, 8);
            sum += __shfl_xor_sync(0xffffffffu, sum, 2, 8);
            sum += __shfl_xor_sync(0xffffffffu, sum, 4, 8);
            l[ii] = l[ii] * alpha + sum;
            m[ii] = mnew;
#pragma unroll
            for (int ee = 0; ee < 8; ee++) o[ii][ee] *= alpha;
            *(float4*)&Ps[(ty * 4 + ii) * PS_STRIDE + tx * 4] =
                make_float4(p[0], p[1], p[2], p[3]);
        }
        __syncthreads();   // Ps written; all done reading K from KV union

        // Load V tile (32 keys x 64 dims), natural layout, into KV union
        const float* vbase = vw + ((size_t)b * SEQ + kt * 32) * DM + h * HD;
        for (int i = tid; i < 32 * 64; i += 128) {
            int j = i >> 6, d = i & 63;
            KV[j * VS_STRIDE + d] = vbase[(size_t)j * DM + d];
        }
        __syncthreads();

        // O += P . V   (each thread 4 rows x 8 dim-cols)
#pragma unroll 8
        for (int j = 0; j < 32; j++) {
            float4 v0 = *(const float4*)&KV[j * VS_STRIDE + tx * 8];
            float4 v1 = *(const float4*)&KV[j * VS_STRIDE + tx * 8 + 4];
            float vv[8] = {v0.x, v0.y, v0.z, v0.w, v1.x, v1.y, v1.z, v1.w};
            float pp[4];
#pragma unroll
            for (int ii = 0; ii < 4; ii++)
                pp[ii] = Ps[(ty * 4 + ii) * PS_STRIDE + j];
#pragma unroll
            for (int ii = 0; ii < 4; ii++)
#pragma unroll
                for (int ee = 0; ee < 8; ee++)
                    o[ii][ee] = fmaf(pp[ii], vv[ee], o[ii][ee]);
        }
    }

    // Normalize and write ctx[b, q, h*64 + e]
    float* obase = ctx + ((size_t)b * SEQ + qt * 64) * DM + h * HD;
#pragma unroll
    for (int ii = 0; ii < 4; ii++) {
        float inv = 1.0f / l[ii];
        float4 w0, w1;
        w0.x = o[ii][0] * inv; w0.y = o[ii][1] * inv;
        w0.z = o[ii][2] * inv; w0.w = o[ii][3] * inv;
        w1.x = o[ii][4] * inv; w1.y = o[ii][5] * inv;
        w1.z = o[ii][6] * inv; w1.w = o[ii][7] * inv;
        size_t row = (size_t)(ty * 4 + ii) * DM + tx * 8;
        *(float4*)&obase[row]     = w0;
        *(float4*)&obase[row + 4] = w1;
    }
}

// ---------------------------------------------------------------------------
extern "C" void kernel_launch(void* const* d_in, const int* in_sizes, int n_in,
                              void* d_out, int out_size)
{
    const float* q    = (const float*)d_in[0];
    const float* k    = (const float*)d_in[1];
    const float* v    = (const float*)d_in[2];
    const int*   mask = (const int*)  d_in[3];
    const float* Wq   = (const float*)d_in[4];
    const float* bq   = (const float*)d_in[5];
    const float* Wk   = (const float*)d_in[6];
    const float* bk   = (const float*)d_in[7];
    const float* Wv   = (const float*)d_in[8];
    const float* bv   = (const float*)d_in[9];
    const float* Wo   = (const float*)d_in[10];
    const float* bo   = (const float*)d_in[11];
    float* out = (float*)d_out;

    void *pqw, *pkw, *pvw, *pctx;
    cudaGetSymbolAddress(&pqw, g_qw);
    cudaGetSymbolAddress(&pkw, g_kw);
    cudaGetSymbolAddress(&pvw, g_vw);
    cudaGetSymbolAddress(&pctx, g_ctx);

    dim3 ggrid(DM / 128, MROWS / 128);   // (8, 32)

    sgemm_bias<<<ggrid, 256>>>(q, Wq, bq, (float*)pqw, MROWS, DM, DM);
    sgemm_bias<<<ggrid, 256>>>(k, Wk, bk, (float*)pkw, MROWS, DM, DM);
    sgemm_bias<<<ggrid, 256>>>(v, Wv, bv, (float*)pvw, MROWS, DM, DM);

    attn_kernel<<<dim3(SEQ / 64, NH, NB), 128>>>(
        (const float*)pqw, (const float*)pkw, (const float*)pvw, mask,
        (float*)pctx);

    sgemm_bias<<<ggrid, 256>>>((const float*)pctx, Wo, bo, out, MROWS, DM, DM);
}

// round 3
// speedup vs baseline: 1.9164x; 1.9120x over previous
#include <cuda_runtime.h>
#include <math.h>

#define SEQ 2048
#define DM 1024
#define NH 16
#define HD 64
#define NB 2
#define MROWS (NB * SEQ)   // 4096

// Scratch (allocation-free rule: __device__ globals)
__device__ float g_qw[MROWS * DM];
__device__ float g_kw[MROWS * DM];
__device__ float g_vw[MROWS * DM];
__device__ float g_ctx[MROWS * DM];

__device__ __forceinline__ unsigned f2tf(float x) {
    unsigned r;
    asm("cvt.rna.tf32.f32 %0, %1;" : "=r"(r) : "f"(x));
    return r;
}

__device__ __forceinline__ void mma_tf32(float c[4], const unsigned a[4],
                                         const unsigned b[2]) {
    asm volatile(
        "mma.sync.aligned.m16n8k8.row.col.f32.tf32.tf32.f32 "
        "{%0,%1,%2,%3}, {%4,%5,%6,%7}, {%8,%9}, {%0,%1,%2,%3};\n"
        : "+f"(c[0]), "+f"(c[1]), "+f"(c[2]), "+f"(c[3])
        : "r"(a[0]), "r"(a[1]), "r"(a[2]), "r"(a[3]), "r"(b[0]), "r"(b[1]));
}

// ---------------------------------------------------------------------------
// tf32 GEMM: C = A(MxK) @ B(KxN) + bias.  128x128 block tile, 256 threads,
// 8 warps each computing 64x32 via m16n8k8 fragments. k-chunk = 32.
// Fragment-load bank math: A-frag addr ~ 4g+t (stride 36 = 4 mod 32) -> 0..31
// distinct; B-frag addr ~ 8t+g (stride 136 = 8 mod 32) -> 0..31 distinct.
// ---------------------------------------------------------------------------
#define GA_S 36
#define GB_S 136

__global__ __launch_bounds__(256) void gemm_tf32(
    const float* __restrict__ A, const float* __restrict__ B,
    const float* __restrict__ bias, float* __restrict__ C,
    int M, int N, int K)
{
    __shared__ unsigned As[128 * GA_S];
    __shared__ unsigned Bs[32 * GB_S];

    const int tid  = threadIdx.x;
    const int lane = tid & 31;
    const int warp = tid >> 5;
    const int g = lane >> 2, t = lane & 3;
    const int wm = (warp >> 2) * 64;   // 0 or 64
    const int wn = (warp & 3) * 32;    // 0..96
    const int bm = blockIdx.y * 128;
    const int bn = blockIdx.x * 128;

    // A loads: row = tid/2, 16 consecutive cols per thread (4 x float4)
    const int arow = tid >> 1, ac0 = (tid & 1) * 16;
    // B loads: row = tid/8, float4 at col (tid&7)*4 + v*32 (coalesced per v)
    const int brow = tid >> 3, bc0 = (tid & 7) * 4;

    float acc[4][4][4];
#pragma unroll
    for (int mi = 0; mi < 4; mi++)
#pragma unroll
        for (int ni = 0; ni < 4; ni++)
#pragma unroll
            for (int e = 0; e < 4; e++) acc[mi][ni][e] = 0.0f;

    for (int k0 = 0; k0 < K; k0 += 32) {
        const float* ap = A + (size_t)(bm + arow) * K + k0 + ac0;
#pragma unroll
        for (int v = 0; v < 4; v++) {
            float4 x = *(const float4*)(ap + v * 4);
            unsigned* d = &As[arow * GA_S + ac0 + v * 4];
            d[0] = f2tf(x.x); d[1] = f2tf(x.y); d[2] = f2tf(x.z); d[3] = f2tf(x.w);
        }
        const float* bp = B + (size_t)(k0 + brow) * N + bn + bc0;
#pragma unroll
        for (int v = 0; v < 4; v++) {
            float4 x = *(const float4*)(bp + v * 32);
            unsigned* d = &Bs[brow * GB_S + bc0 + v * 32];
            d[0] = f2tf(x.x); d[1] = f2tf(x.y); d[2] = f2tf(x.z); d[3] = f2tf(x.w);
        }
        __syncthreads();

#pragma unroll
        for (int kk = 0; kk < 32; kk += 8) {
            unsigned af[4][4], bf[4][2];
#pragma unroll
            for (int mi = 0; mi < 4; mi++) {
                int r = wm + mi * 16;
                af[mi][0] = As[(r + g)     * GA_S + kk + t];
                af[mi][1] = As[(r + g + 8) * GA_S + kk + t];
                af[mi][2] = As[(r + g)     * GA_S + kk + t + 4];
                af[mi][3] = As[(r + g + 8) * GA_S + kk + t + 4];
            }
#pragma unroll
            for (int ni = 0; ni < 4; ni++) {
                int c = wn + ni * 8;
                bf[ni][0] = Bs[(kk + t)     * GB_S + c + g];
                bf[ni][1] = Bs[(kk + t + 4) * GB_S + c + g];
            }
#pragma unroll
            for (int mi = 0; mi < 4; mi++)
#pragma unroll
                for (int ni = 0; ni < 4; ni++)
                    mma_tf32(acc[mi][ni], af[mi], bf[ni]);
        }
        __syncthreads();
    }

    // Epilogue: c0 (g, 2t), c1 (g, 2t+1), c2 (g+8, 2t), c3 (g+8, 2t+1)
#pragma unroll
    for (int mi = 0; mi < 4; mi++) {
        int r0 = bm + wm + mi * 16 + g;
#pragma unroll
        for (int ni = 0; ni < 4; ni++) {
            int cb = bn + wn + ni * 8 + 2 * t;
            float b0 = bias[cb], b1 = bias[cb + 1];
            float2 v0 = make_float2(acc[mi][ni][0] + b0, acc[mi][ni][1] + b1);
            float2 v1 = make_float2(acc[mi][ni][2] + b0, acc[mi][ni][3] + b1);
            *(float2*)&C[(size_t)r0 * N + cb]       = v0;
            *(float2*)&C[(size_t)(r0 + 8) * N + cb] = v1;
        }
    }
}

// ---------------------------------------------------------------------------
// Fused flash-attention with tf32 mma. One block = (b, h, 64-query tile).
// 4 warps x 16 query rows each. Key tiles of 64. Q fragments in registers.
// P converted C-layout -> A-layout with register shuffles (no Ps smem).
// Masking identical to reference: s -= (1-m)*1e12 before online softmax.
// ---------------------------------------------------------------------------
#define KS_S 72   // Ks: K transposed [d][key], stride 72 (8 mod 32 -> B-frags clean)
#define VS_S 72   // Vs: V natural [key][d], stride 72

__global__ __launch_bounds__(128) void attn_mma(
    const float* __restrict__ qw, const float* __restrict__ kw,
    const float* __restrict__ vw, const int* __restrict__ vmask,
    float* __restrict__ ctx)
{
    __shared__ unsigned Ks[64 * KS_S];
    __shared__ unsigned Vs[64 * VS_S];
    __shared__ float Ms[64];

    const int tid  = threadIdx.x;
    const int lane = tid & 31;
    const int warp = tid >> 5;
    const int g = lane >> 2, t = lane & 3;
    const int qrow0 = warp * 16;
    const int qt = blockIdx.x, h = blockIdx.y, b = blockIdx.z;

    // Stage Q (pre-scaled by 1/8) through Ks as [row][d], read A-fragments.
    const float* qbase = qw + ((size_t)b * SEQ + qt * 64) * DM + h * HD;
    for (int i = tid; i < 64 * 64; i += 128) {
        int r = i >> 6, d = i & 63;
        Ks[r * KS_S + d] = f2tf(qbase[(size_t)r * DM + d] * 0.125f);
    }
    __syncthreads();
    unsigned qf[8][4];
#pragma unroll
    for (int kf = 0; kf < 8; kf++) {
        qf[kf][0] = Ks[(qrow0 + g)     * KS_S + kf * 8 + t];
        qf[kf][1] = Ks[(qrow0 + g + 8) * KS_S + kf * 8 + t];
        qf[kf][2] = Ks[(qrow0 + g)     * KS_S + kf * 8 + t + 4];
        qf[kf][3] = Ks[(qrow0 + g + 8) * KS_S + kf * 8 + t + 4];
    }

    float m0 = -1e30f, m1 = -1e30f, l0 = 0.0f, l1 = 0.0f;
    float o[8][4];
#pragma unroll
    for (int nf = 0; nf < 8; nf++)
#pragma unroll
        for (int e = 0; e < 4; e++) o[nf][e] = 0.0f;

    for (int kt = 0; kt < SEQ / 64; kt++) {
        __syncthreads();   // prev tile's mma reads done before overwrite
        const float* kbase = kw + ((size_t)b * SEQ + kt * 64) * DM + h * HD;
        for (int i = tid; i < 64 * 64; i += 128) {
            int j = i >> 6, d = i & 63;   // j = key, d = dim
            Ks[d * KS_S + j] = f2tf(kbase[(size_t)j * DM + d]);
        }
        const float* vbase = vw + ((size_t)b * SEQ + kt * 64) * DM + h * HD;
        for (int i = tid; i < 64 * 64; i += 128) {
            int j = i >> 6, d = i & 63;
            Vs[j * VS_S + d] = f2tf(vbase[(size_t)j * DM + d]);
        }
        if (tid < 64) Ms[tid] = (float)vmask[b * SEQ + kt * 64 + tid];
        __syncthreads();

        // S = Qscaled . K^T  (16 rows x 64 keys per warp)
        float s[8][4];
#pragma unroll
        for (int nf = 0; nf < 8; nf++)
#pragma unroll
            for (int e = 0; e < 4; e++) s[nf][e] = 0.0f;
#pragma unroll
        for (int nf = 0; nf < 8; nf++) {
#pragma unroll
            for (int kf = 0; kf < 8; kf++) {
                unsigned bfr[2];
                bfr[0] = Ks[(kf * 8 + t)     * KS_S + nf * 8 + g];
                bfr[1] = Ks[(kf * 8 + t + 4) * KS_S + nf * 8 + g];
                mma_tf32(s[nf], qf[kf], bfr);
            }
        }

        // Mask + online softmax. Rows: g (regs 0,1), g+8 (regs 2,3).
        float mx0 = -1e30f, mx1 = -1e30f;
#pragma unroll
        for (int nf = 0; nf < 8; nf++) {
            float pen0 = (1.0f - Ms[nf * 8 + 2 * t])     * 1e12f;
            float pen1 = (1.0f - Ms[nf * 8 + 2 * t + 1]) * 1e12f;
            s[nf][0] -= pen0; s[nf][1] -= pen1;
            s[nf][2] -= pen0; s[nf][3] -= pen1;
            mx0 = fmaxf(mx0, fmaxf(s[nf][0], s[nf][1]));
            mx1 = fmaxf(mx1, fmaxf(s[nf][2], s[nf][3]));
        }
        mx0 = fmaxf(mx0, __shfl_xor_sync(0xffffffffu, mx0, 1));
        mx0 = fmaxf(mx0, __shfl_xor_sync(0xffffffffu, mx0, 2));
        mx1 = fmaxf(mx1, __shfl_xor_sync(0xffffffffu, mx1, 1));
        mx1 = fmaxf(mx1, __shfl_xor_sync(0xffffffffu, mx1, 2));
        float mn0 = fmaxf(m0, mx0), mn1 = fmaxf(m1, mx1);
        float al0 = __expf(m0 - mn0), al1 = __expf(m1 - mn1);
        m0 = mn0; m1 = mn1;
        float sum0 = 0.0f, sum1 = 0.0f;
#pragma unroll
        for (int nf = 0; nf < 8; nf++) {
            s[nf][0] = __expf(s[nf][0] - mn0);
            s[nf][1] = __expf(s[nf][1] - mn0);
            s[nf][2] = __expf(s[nf][2] - mn1);
            s[nf][3] = __expf(s[nf][3] - mn1);
            sum0 += s[nf][0] + s[nf][1];
            sum1 += s[nf][2] + s[nf][3];
        }
        sum0 += __shfl_xor_sync(0xffffffffu, sum0, 1);
        sum0 += __shfl_xor_sync(0xffffffffu, sum0, 2);
        sum1 += __shfl_xor_sync(0xffffffffu, sum1, 1);
        sum1 += __shfl_xor_sync(0xffffffffu, sum1, 2);
        l0 = l0 * al0 + sum0;
        l1 = l1 * al1 + sum1;
#pragma unroll
        for (int nf = 0; nf < 8; nf++) {
            o[nf][0] *= al0; o[nf][1] *= al0;
            o[nf][2] *= al1; o[nf][3] *= al1;
        }

        // O += P . V : build A-frag of P from C-layout via shuffles.
        // A-frag kf needs P(row, kf*8 + t) and (.. + t+4):
        //   src lane = g*4 + t/2 (and +2), reg parity = t&1.
        const int srcA = (lane & ~3) | (t >> 1);
        const int srcB = srcA + 2;
        const bool odd = (t & 1);
#pragma unroll
        for (int kf = 0; kf < 8; kf++) {
            float x0 = __shfl_sync(0xffffffffu, s[kf][0], srcA);
            float x1 = __shfl_sync(0xffffffffu, s[kf][1], srcA);
            float x2 = __shfl_sync(0xffffffffu, s[kf][2], srcA);
            float x3 = __shfl_sync(0xffffffffu, s[kf][3], srcA);
            float y0 = __shfl_sync(0xffffffffu, s[kf][0], srcB);
            float y1 = __shfl_sync(0xffffffffu, s[kf][1], srcB);
            float y2 = __shfl_sync(0xffffffffu, s[kf][2], srcB);
            float y3 = __shfl_sync(0xffffffffu, s[kf][3], srcB);
            unsigned af[4];
            af[0] = f2tf(odd ? x1 : x0);   // P(g,    kf*8+t)
            af[1] = f2tf(odd ? x3 : x2);   // P(g+8,  kf*8+t)
            af[2] = f2tf(odd ? y1 : y0);   // P(g,    kf*8+t+4)
            af[3] = f2tf(odd ? y3 : y2);   // P(g+8,  kf*8+t+4)
#pragma unroll
            for (int nf = 0; nf < 8; nf++) {
                unsigned bfr[2];
                bfr[0] = Vs[(kf * 8 + t)     * VS_S + nf * 8 + g];
                bfr[1] = Vs[(kf * 8 + t + 4) * VS_S + nf * 8 + g];
                mma_tf32(o[nf], af, bfr);
            }
        }
    }

    // Normalize, write ctx[b, q, h*64 + d]
    float inv0 = 1.0f / l0, inv1 = 1.0f / l1;
    float* obase = ctx + ((size_t)b * SEQ + qt * 64 + qrow0) * DM + h * HD;
#pragma unroll
    for (int nf = 0; nf < 8; nf++) {
        int col = nf * 8 + 2 * t;
        float2 v0 = make_float2(o[nf][0] * inv0, o[nf][1] * inv0);
        float2 v1 = make_float2(o[nf][2] * inv1, o[nf][3] * inv1);
        *(float2*)&obase[(size_t)g * DM + col]       = v0;
        *(float2*)&obase[(size_t)(g + 8) * DM + col] = v1;
    }
}

// ---------------------------------------------------------------------------
extern "C" void kernel_launch(void* const* d_in, const int* in_sizes, int n_in,
                              void* d_out, int out_size)
{
    const float* q    = (const float*)d_in[0];
    const float* k    = (const float*)d_in[1];
    const float* v    = (const float*)d_in[2];
    const int*   mask = (const int*)  d_in[3];
    const float* Wq   = (const float*)d_in[4];
    const float* bq   = (const float*)d_in[5];
    const float* Wk   = (const float*)d_in[6];
    const float* bk   = (const float*)d_in[7];
    const float* Wv   = (const float*)d_in[8];
    const float* bv   = (const float*)d_in[9];
    const float* Wo   = (const float*)d_in[10];
    const float* bo   = (const float*)d_in[11];
    float* out = (float*)d_out;

    void *pqw, *pkw, *pvw, *pctx;
    cudaGetSymbolAddress(&pqw, g_qw);
    cudaGetSymbolAddress(&pkw, g_kw);
    cudaGetSymbolAddress(&pvw, g_vw);
    cudaGetSymbolAddress(&pctx, g_ctx);

    dim3 ggrid(DM / 128, MROWS / 128);   // (8, 32)

    gemm_tf32<<<ggrid, 256>>>(q, Wq, bq, (float*)pqw, MROWS, DM, DM);
    gemm_tf32<<<ggrid, 256>>>(k, Wk, bk, (float*)pkw, MROWS, DM, DM);
    gemm_tf32<<<ggrid, 256>>>(v, Wv, bv, (float*)pvw, MROWS, DM, DM);

    attn_mma<<<dim3(SEQ / 64, NH, NB), 128>>>(
        (const float*)pqw, (const float*)pkw, (const float*)pvw, mask,
        (float*)pctx);

    gemm_tf32<<<ggrid, 256>>>((const float*)pctx, Wo, bo, out, MROWS, DM, DM);
}

// round 4
// speedup vs baseline: 3.1579x; 1.6478x over previous
#include <cuda_runtime.h>
#include <math.h>

#define SEQ 2048
#define DM 1024
#define NH 16
#define HD 64
#define NB 2
#define MROWS (NB * SEQ)   // 4096

// Scratch (allocation-free rule: __device__ globals).
// qw/kw/vw hold tf32 BIT PATTERNS (written by GEMM epilogue); ctx is fp32.
__device__ float g_qw[MROWS * DM];
__device__ float g_kw[MROWS * DM];
__device__ float g_vw[MROWS * DM];
__device__ float g_ctx[MROWS * DM];

__device__ __forceinline__ unsigned f2tf(float x) {
    unsigned r;
    asm("cvt.rna.tf32.f32 %0, %1;" : "=r"(r) : "f"(x));
    return r;
}

__device__ __forceinline__ void mma_tf32(float c[4], const unsigned a[4],
                                         const unsigned b[2]) {
    asm volatile(
        "mma.sync.aligned.m16n8k8.row.col.f32.tf32.tf32.f32 "
        "{%0,%1,%2,%3}, {%4,%5,%6,%7}, {%8,%9}, {%0,%1,%2,%3};\n"
        : "+f"(c[0]), "+f"(c[1]), "+f"(c[2]), "+f"(c[3])
        : "r"(a[0]), "r"(a[1]), "r"(a[2]), "r"(a[3]), "r"(b[0]), "r"(b[1]));
}

__device__ __forceinline__ void cp_cg16(float* dst, const float* src) {
    unsigned u = (unsigned)__cvta_generic_to_shared(dst);
    asm volatile("cp.async.cg.shared.global [%0], [%1], 16;" :: "r"(u), "l"(src));
}

// ---------------------------------------------------------------------------
// tf32 GEMM: C = (A(MxK) @ B(KxN) + bias) * scale, stored fp32 or tf32 bits.
// 128x128 block tile, 256 threads, 8 warps x (64x32) via m16n8k8.
// ---------------------------------------------------------------------------
#define GA_S 36
#define GB_S 136

__global__ __launch_bounds__(256) void gemm_tf32(
    const float* __restrict__ A, const float* __restrict__ B,
    const float* __restrict__ bias, float* __restrict__ C,
    int M, int N, int K, float scale, int conv)
{
    __shared__ unsigned As[128 * GA_S];
    __shared__ unsigned Bs[32 * GB_S];

    const int tid  = threadIdx.x;
    const int lane = tid & 31;
    const int warp = tid >> 5;
    const int g = lane >> 2, t = lane & 3;
    const int wm = (warp >> 2) * 64;
    const int wn = (warp & 3) * 32;
    const int bm = blockIdx.y * 128;
    const int bn = blockIdx.x * 128;

    const int arow = tid >> 1, ac0 = (tid & 1) * 16;
    const int brow = tid >> 3, bc0 = (tid & 7) * 4;

    float acc[4][4][4];
#pragma unroll
    for (int mi = 0; mi < 4; mi++)
#pragma unroll
        for (int ni = 0; ni < 4; ni++)
#pragma unroll
            for (int e = 0; e < 4; e++) acc[mi][ni][e] = 0.0f;

    for (int k0 = 0; k0 < K; k0 += 32) {
        const float* ap = A + (size_t)(bm + arow) * K + k0 + ac0;
#pragma unroll
        for (int v = 0; v < 4; v++) {
            float4 x = *(const float4*)(ap + v * 4);
            unsigned* d = &As[arow * GA_S + ac0 + v * 4];
            d[0] = f2tf(x.x); d[1] = f2tf(x.y); d[2] = f2tf(x.z); d[3] = f2tf(x.w);
        }
        const float* bp = B + (size_t)(k0 + brow) * N + bn + bc0;
#pragma unroll
        for (int v = 0; v < 4; v++) {
            float4 x = *(const float4*)(bp + v * 32);
            unsigned* d = &Bs[brow * GB_S + bc0 + v * 32];
            d[0] = f2tf(x.x); d[1] = f2tf(x.y); d[2] = f2tf(x.z); d[3] = f2tf(x.w);
        }
        __syncthreads();

#pragma unroll
        for (int kk = 0; kk < 32; kk += 8) {
            unsigned af[4][4], bf[4][2];
#pragma unroll
            for (int mi = 0; mi < 4; mi++) {
                int r = wm + mi * 16;
                af[mi][0] = As[(r + g)     * GA_S + kk + t];
                af[mi][1] = As[(r + g + 8) * GA_S + kk + t];
                af[mi][2] = As[(r + g)     * GA_S + kk + t + 4];
                af[mi][3] = As[(r + g + 8) * GA_S + kk + t + 4];
            }
#pragma unroll
            for (int ni = 0; ni < 4; ni++) {
                int c = wn + ni * 8;
                bf[ni][0] = Bs[(kk + t)     * GB_S + c + g];
                bf[ni][1] = Bs[(kk + t + 4) * GB_S + c + g];
            }
#pragma unroll
            for (int mi = 0; mi < 4; mi++)
#pragma unroll
                for (int ni = 0; ni < 4; ni++)
                    mma_tf32(acc[mi][ni], af[mi], bf[ni]);
        }
        __syncthreads();
    }

#pragma unroll
    for (int mi = 0; mi < 4; mi++) {
        int r0 = bm + wm + mi * 16 + g;
#pragma unroll
        for (int ni = 0; ni < 4; ni++) {
            int cb = bn + wn + ni * 8 + 2 * t;
            float b0 = bias[cb], b1 = bias[cb + 1];
            float x00 = (acc[mi][ni][0] + b0) * scale;
            float x01 = (acc[mi][ni][1] + b1) * scale;
            float x10 = (acc[mi][ni][2] + b0) * scale;
            float x11 = (acc[mi][ni][3] + b1) * scale;
            float2 v0, v1;
            if (conv) {
                v0 = make_float2(__uint_as_float(f2tf(x00)),
                                 __uint_as_float(f2tf(x01)));
                v1 = make_float2(__uint_as_float(f2tf(x10)),
                                 __uint_as_float(f2tf(x11)));
            } else {
                v0 = make_float2(x00, x01);
                v1 = make_float2(x10, x11);
            }
            *(float2*)&C[(size_t)r0 * N + cb]       = v0;
            *(float2*)&C[(size_t)(r0 + 8) * N + cb] = v1;
        }
    }
}

// ---------------------------------------------------------------------------
// Flash-attention, tf32 mma, cp.async double-buffered K/V pipeline.
// Block = (64-query tile, head, batch), 4 warps x 16 rows.
// K and V in NATURAL [key][d] smem layout, stride 76:
//   S B-frag bank index = (12g+t) mod 32  -> 32 distinct (conflict-free)
//   V B-frag bank index = (12t+g) mod 32  -> 32 distinct (conflict-free)
// All tf32 conversions pre-done by GEMM epilogues; loop is copy + mma only.
// ---------------------------------------------------------------------------
#define AT_S 76
#define KTILE 64
#define NT (SEQ / KTILE)
#define STAGE_FLOATS (KTILE * AT_S * 2 + 64)   // Ks + Vs + mask

extern __shared__ float sm_dyn[];

__device__ __forceinline__ void prefetch_tile(
    float* stage, const float* kb, const float* vb, const int* mb, int tid)
{
    float* Ks = stage;
    float* Vs = stage + KTILE * AT_S;
    float* Mk = Vs + KTILE * AT_S;
#pragma unroll
    for (int j = 0; j < 8; j++) {
        int c = tid + j * 128;
        int r = c >> 4, col = (c & 15) << 2;
        cp_cg16(Ks + r * AT_S + col, kb + (size_t)r * DM + col);
        cp_cg16(Vs + r * AT_S + col, vb + (size_t)r * DM + col);
    }
    if (tid < 16) cp_cg16(Mk + tid * 4, (const float*)(mb + tid * 4));
}

__global__ __launch_bounds__(128) void attn_mma(
    const float* __restrict__ qw, const float* __restrict__ kw,
    const float* __restrict__ vw, const int* __restrict__ vmask,
    float* __restrict__ ctx)
{
    const int tid  = threadIdx.x;
    const int lane = tid & 31;
    const int warp = tid >> 5;
    const int g = lane >> 2, t = lane & 3;
    const int qrow0 = warp * 16;
    const int qt = blockIdx.x, h = blockIdx.y, b = blockIdx.z;

    // Q fragments direct from global (tf32 bits, pre-scaled by 1/8).
    const unsigned* qp = (const unsigned*)qw
                       + ((size_t)b * SEQ + qt * 64) * DM + h * HD;
    unsigned qf[8][4];
#pragma unroll
    for (int kf = 0; kf < 8; kf++) {
        qf[kf][0] = __ldg(qp + (size_t)(qrow0 + g)     * DM + kf * 8 + t);
        qf[kf][1] = __ldg(qp + (size_t)(qrow0 + g + 8) * DM + kf * 8 + t);
        qf[kf][2] = __ldg(qp + (size_t)(qrow0 + g)     * DM + kf * 8 + t + 4);
        qf[kf][3] = __ldg(qp + (size_t)(qrow0 + g + 8) * DM + kf * 8 + t + 4);
    }

    const float* kbase = kw + ((size_t)b * SEQ) * DM + h * HD;
    const float* vbase = vw + ((size_t)b * SEQ) * DM + h * HD;
    const int*   mbase = vmask + b * SEQ;

    float m0 = -1e30f, m1 = -1e30f, l0 = 0.0f, l1 = 0.0f;
    float o[8][4];
#pragma unroll
    for (int nf = 0; nf < 8; nf++)
#pragma unroll
        for (int e = 0; e < 4; e++) o[nf][e] = 0.0f;

    prefetch_tile(sm_dyn, kbase, vbase, mbase, tid);
    asm volatile("cp.async.commit_group;" ::: "memory");

    const int srcA = (lane & ~3) | (t >> 1);
    const int srcB = srcA + 2;
    const bool odd = (t & 1);

    for (int kt = 0; kt < NT; kt++) {
        const int st = kt & 1;
        asm volatile("cp.async.wait_group 0;" ::: "memory");
        __syncthreads();   // tile kt arrived; all warps done with buffer st^1
        if (kt + 1 < NT) {
            prefetch_tile(sm_dyn + (st ^ 1) * STAGE_FLOATS,
                          kbase + (size_t)(kt + 1) * KTILE * DM,
                          vbase + (size_t)(kt + 1) * KTILE * DM,
                          mbase + (kt + 1) * KTILE, tid);
            asm volatile("cp.async.commit_group;" ::: "memory");
        }

        const unsigned* Ks = (const unsigned*)(sm_dyn + st * STAGE_FLOATS);
        const unsigned* Vs = Ks + KTILE * AT_S;
        const int*      Mk = (const int*)(Vs + KTILE * AT_S);

        // S = Qs . K^T  (B-frag from natural K layout)
        float s[8][4];
#pragma unroll
        for (int nf = 0; nf < 8; nf++)
#pragma unroll
            for (int e = 0; e < 4; e++) s[nf][e] = 0.0f;
#pragma unroll
        for (int nf = 0; nf < 8; nf++) {
#pragma unroll
            for (int kf = 0; kf < 8; kf++) {
                unsigned bfr[2];
                bfr[0] = Ks[(nf * 8 + g) * AT_S + kf * 8 + t];
                bfr[1] = Ks[(nf * 8 + g) * AT_S + kf * 8 + t + 4];
                mma_tf32(s[nf], qf[kf], bfr);
            }
        }

        // Mask + online softmax (rows g -> regs 0,1; g+8 -> regs 2,3)
        float mx0 = -1e30f, mx1 = -1e30f;
#pragma unroll
        for (int nf = 0; nf < 8; nf++) {
            float pen0 = Mk[nf * 8 + 2 * t]     ? 0.0f : 1e12f;
            float pen1 = Mk[nf * 8 + 2 * t + 1] ? 0.0f : 1e12f;
            s[nf][0] -= pen0; s[nf][1] -= pen1;
            s[nf][2] -= pen0; s[nf][3] -= pen1;
            mx0 = fmaxf(mx0, fmaxf(s[nf][0], s[nf][1]));
            mx1 = fmaxf(mx1, fmaxf(s[nf][2], s[nf][3]));
        }
        mx0 = fmaxf(mx0, __shfl_xor_sync(0xffffffffu, mx0, 1));
        mx0 = fmaxf(mx0, __shfl_xor_sync(0xffffffffu, mx0, 2));
        mx1 = fmaxf(mx1, __shfl_xor_sync(0xffffffffu, mx1, 1));
        mx1 = fmaxf(mx1, __shfl_xor_sync(0xffffffffu, mx1, 2));
        float mn0 = fmaxf(m0, mx0), mn1 = fmaxf(m1, mx1);
        float al0 = __expf(m0 - mn0), al1 = __expf(m1 - mn1);
        m0 = mn0; m1 = mn1;
        float sum0 = 0.0f, sum1 = 0.0f;
#pragma unroll
        for (int nf = 0; nf < 8; nf++) {
            s[nf][0] = __expf(s[nf][0] - mn0);
            s[nf][1] = __expf(s[nf][1] - mn0);
            s[nf][2] = __expf(s[nf][2] - mn1);
            s[nf][3] = __expf(s[nf][3] - mn1);
            sum0 += s[nf][0] + s[nf][1];
            sum1 += s[nf][2] + s[nf][3];
        }
        sum0 += __shfl_xor_sync(0xffffffffu, sum0, 1);
        sum0 += __shfl_xor_sync(0xffffffffu, sum0, 2);
        sum1 += __shfl_xor_sync(0xffffffffu, sum1, 1);
        sum1 += __shfl_xor_sync(0xffffffffu, sum1, 2);
        l0 = l0 * al0 + sum0;
        l1 = l1 * al1 + sum1;
#pragma unroll
        for (int nf = 0; nf < 8; nf++) {
            o[nf][0] *= al0; o[nf][1] *= al0;
            o[nf][2] *= al1; o[nf][3] *= al1;
        }

        // O += P . V : C-layout -> A-layout via shuffles; V natural layout.
#pragma unroll
        for (int kf = 0; kf < 8; kf++) {
            float x0 = __shfl_sync(0xffffffffu, s[kf][0], srcA);
            float x1 = __shfl_sync(0xffffffffu, s[kf][1], srcA);
            float x2 = __shfl_sync(0xffffffffu, s[kf][2], srcA);
            float x3 = __shfl_sync(0xffffffffu, s[kf][3], srcA);
            float y0 = __shfl_sync(0xffffffffu, s[kf][0], srcB);
            float y1 = __shfl_sync(0xffffffffu, s[kf][1], srcB);
            float y2 = __shfl_sync(0xffffffffu, s[kf][2], srcB);
            float y3 = __shfl_sync(0xffffffffu, s[kf][3], srcB);
            unsigned af[4];
            af[0] = f2tf(odd ? x1 : x0);
            af[1] = f2tf(odd ? x3 : x2);
            af[2] = f2tf(odd ? y1 : y0);
            af[3] = f2tf(odd ? y3 : y2);
#pragma unroll
            for (int nf = 0; nf < 8; nf++) {
                unsigned bfr[2];
                bfr[0] = Vs[(kf * 8 + t)     * AT_S + nf * 8 + g];
                bfr[1] = Vs[(kf * 8 + t + 4) * AT_S + nf * 8 + g];
                mma_tf32(o[nf], af, bfr);
            }
        }
    }

    // Normalize and write ctx (fp32)
    float inv0 = 1.0f / l0, inv1 = 1.0f / l1;
    float* obase = ctx + ((size_t)b * SEQ + qt * 64 + qrow0) * DM + h * HD;
#pragma unroll
    for (int nf = 0; nf < 8; nf++) {
        int col = nf * 8 + 2 * t;
        float2 v0 = make_float2(o[nf][0] * inv0, o[nf][1] * inv0);
        float2 v1 = make_float2(o[nf][2] * inv1, o[nf][3] * inv1);
        *(float2*)&obase[(size_t)g * DM + col]       = v0;
        *(float2*)&obase[(size_t)(g + 8) * DM + col] = v1;
    }
}

// ---------------------------------------------------------------------------
extern "C" void kernel_launch(void* const* d_in, const int* in_sizes, int n_in,
                              void* d_out, int out_size)
{
    const float* q    = (const float*)d_in[0];
    const float* k    = (const float*)d_in[1];
    const float* v    = (const float*)d_in[2];
    const int*   mask = (const int*)  d_in[3];
    const float* Wq   = (const float*)d_in[4];
    const float* bq   = (const float*)d_in[5];
    const float* Wk   = (const float*)d_in[6];
    const float* bk   = (const float*)d_in[7];
    const float* Wv   = (const float*)d_in[8];
    const float* bv   = (const float*)d_in[9];
    const float* Wo   = (const float*)d_in[10];
    const float* bo   = (const float*)d_in[11];
    float* out = (float*)d_out;

    void *pqw, *pkw, *pvw, *pctx;
    cudaGetSymbolAddress(&pqw, g_qw);
    cudaGetSymbolAddress(&pkw, g_kw);
    cudaGetSymbolAddress(&pvw, g_vw);
    cudaGetSymbolAddress(&pctx, g_ctx);

    const int attn_smem = 2 * STAGE_FLOATS * (int)sizeof(float);
    cudaFuncSetAttribute(attn_mma,
                         cudaFuncAttributeMaxDynamicSharedMemorySize, attn_smem);

    dim3 ggrid(DM / 128, MROWS / 128);   // (8, 32)

    // Projections -> tf32 bit patterns (Q pre-scaled by 1/sqrt(64))
    gemm_tf32<<<ggrid, 256>>>(q, Wq, bq, (float*)pqw, MROWS, DM, DM, 0.125f, 1);
    gemm_tf32<<<ggrid, 256>>>(k, Wk, bk, (float*)pkw, MROWS, DM, DM, 1.0f, 1);
    gemm_tf32<<<ggrid, 256>>>(v, Wv, bv, (float*)pvw, MROWS, DM, DM, 1.0f, 1);

    attn_mma<<<dim3(SEQ / 64, NH, NB), 128, attn_smem>>>(
        (const float*)pqw, (const float*)pkw, (const float*)pvw, mask,
        (float*)pctx);

    // Output projection (fp32 out)
    gemm_tf32<<<ggrid, 256>>>((const float*)pctx, Wo, bo, out,
                              MROWS, DM, DM, 1.0f, 0);
}

// round 5
// speedup vs baseline: 3.3568x; 1.0630x over previous
#include <cuda_runtime.h>
#include <math.h>

#define SEQ 2048
#define DM 1024
#define NH 16
#define HD 64
#define NB 2
#define MROWS (NB * SEQ)   // 4096

// Scratch (__device__ globals; allocation-free rule).
// All hold tf32 BIT PATTERNS except where noted.
__device__ unsigned g_qt[MROWS * DM];    // tf32(q)
__device__ unsigned g_kt[MROWS * DM];    // tf32(k)
__device__ unsigned g_vt[MROWS * DM];    // tf32(v)
__device__ unsigned g_w4[4 * DM * DM];   // tf32(Wq|Wk|Wv|Wo)
__device__ unsigned g_qw[MROWS * DM];    // tf32(proj Q * 0.125)
__device__ unsigned g_kw[MROWS * DM];    // tf32(proj K)
__device__ unsigned g_vw[MROWS * DM];    // tf32(proj V)
__device__ unsigned g_ctx[MROWS * DM];   // tf32(attention output)

__device__ __forceinline__ unsigned f2tf(float x) {
    unsigned r;
    asm("cvt.rna.tf32.f32 %0, %1;" : "=r"(r) : "f"(x));
    return r;
}

__device__ __forceinline__ void mma_tf32(float c[4], const unsigned a[4],
                                         const unsigned b[2]) {
    asm volatile(
        "mma.sync.aligned.m16n8k8.row.col.f32.tf32.tf32.f32 "
        "{%0,%1,%2,%3}, {%4,%5,%6,%7}, {%8,%9}, {%0,%1,%2,%3};\n"
        : "+f"(c[0]), "+f"(c[1]), "+f"(c[2]), "+f"(c[3])
        : "r"(a[0]), "r"(a[1]), "r"(a[2]), "r"(a[3]), "r"(b[0]), "r"(b[1]));
}

__device__ __forceinline__ void cp_cg16(void* dst, const void* src) {
    unsigned u = (unsigned)__cvta_generic_to_shared(dst);
    asm volatile("cp.async.cg.shared.global [%0], [%1], 16;" :: "r"(u), "l"(src));
}

extern __shared__ float sm_dyn[];

// ---------------------------------------------------------------------------
// Elementwise fp32 -> tf32 bit conversion (vectorized).
// ---------------------------------------------------------------------------
__global__ __launch_bounds__(256) void to_tf32_k(
    const float4* __restrict__ in, uint4* __restrict__ out, int n4)
{
    int i = blockIdx.x * 256 + threadIdx.x;
    if (i < n4) {
        float4 x = in[i];
        uint4 y;
        y.x = f2tf(x.x); y.y = f2tf(x.y); y.z = f2tf(x.z); y.w = f2tf(x.w);
        out[i] = y;
    }
}

// ---------------------------------------------------------------------------
// tf32 GEMM on pre-converted bits, cp.async double-buffered.
// C = (A @ B + bias) * scale; out fp32 or tf32 bits.
// 128x128 block, 256 threads, 8 warps x (64x32) m16n8k8 tiles.
// ---------------------------------------------------------------------------
#define GA_S 36
#define GB_S 136
#define GEMM_STAGE_A (128 * GA_S)
#define GEMM_STAGE_B (32 * GB_S)
#define GEMM_SMEM ((2 * (GEMM_STAGE_A + GEMM_STAGE_B)) * (int)sizeof(float))

__device__ __forceinline__ void gemm_prefetch(
    unsigned* As, unsigned* Bs, const unsigned* A, const unsigned* B,
    int N, int K, int bm, int bn, int k0, int tid)
{
    const int arow = tid >> 1, ac0 = (tid & 1) * 16;
    const unsigned* ap = A + (size_t)(bm + arow) * K + k0 + ac0;
#pragma unroll
    for (int v = 0; v < 4; v++)
        cp_cg16(&As[arow * GA_S + ac0 + v * 4], ap + v * 4);
    const int brow = tid >> 3, bc0 = (tid & 7) * 4;
    const unsigned* bp = B + (size_t)(k0 + brow) * N + bn + bc0;
#pragma unroll
    for (int v = 0; v < 4; v++)
        cp_cg16(&Bs[brow * GB_S + bc0 + v * 32], bp + v * 32);
}

__global__ __launch_bounds__(256) void gemm_tf32(
    const unsigned* __restrict__ A, const unsigned* __restrict__ B,
    const float* __restrict__ bias, float* __restrict__ C,
    int M, int N, int K, float scale, int conv)
{
    unsigned* As0 = (unsigned*)sm_dyn;
    unsigned* Bs0 = As0 + 2 * GEMM_STAGE_A;

    const int tid  = threadIdx.x;
    const int lane = tid & 31;
    const int warp = tid >> 5;
    const int g = lane >> 2, t = lane & 3;
    const int wm = (warp >> 2) * 64;
    const int wn = (warp & 3) * 32;
    const int bm = blockIdx.y * 128;
    const int bn = blockIdx.x * 128;

    float acc[4][4][4];
#pragma unroll
    for (int mi = 0; mi < 4; mi++)
#pragma unroll
        for (int ni = 0; ni < 4; ni++)
#pragma unroll
            for (int e = 0; e < 4; e++) acc[mi][ni][e] = 0.0f;

    gemm_prefetch(As0, Bs0, A, B, N, K, bm, bn, 0, tid);
    asm volatile("cp.async.commit_group;" ::: "memory");

    const int NKI = K / 32;
    for (int i = 0; i < NKI; i++) {
        const int st = i & 1;
        asm volatile("cp.async.wait_group 0;" ::: "memory");
        __syncthreads();
        if (i + 1 < NKI) {
            gemm_prefetch(As0 + (st ^ 1) * GEMM_STAGE_A,
                          Bs0 + (st ^ 1) * GEMM_STAGE_B,
                          A, B, N, K, bm, bn, (i + 1) * 32, tid);
            asm volatile("cp.async.commit_group;" ::: "memory");
        }
        const unsigned* As = As0 + st * GEMM_STAGE_A;
        const unsigned* Bs = Bs0 + st * GEMM_STAGE_B;

#pragma unroll
        for (int kk = 0; kk < 32; kk += 8) {
            unsigned af[4][4], bf[4][2];
#pragma unroll
            for (int mi = 0; mi < 4; mi++) {
                int r = wm + mi * 16;
                af[mi][0] = As[(r + g)     * GA_S + kk + t];
                af[mi][1] = As[(r + g + 8) * GA_S + kk + t];
                af[mi][2] = As[(r + g)     * GA_S + kk + t + 4];
                af[mi][3] = As[(r + g + 8) * GA_S + kk + t + 4];
            }
#pragma unroll
            for (int ni = 0; ni < 4; ni++) {
                int c = wn + ni * 8;
                bf[ni][0] = Bs[(kk + t)     * GB_S + c + g];
                bf[ni][1] = Bs[(kk + t + 4) * GB_S + c + g];
            }
#pragma unroll
            for (int mi = 0; mi < 4; mi++)
#pragma unroll
                for (int ni = 0; ni < 4; ni++)
                    mma_tf32(acc[mi][ni], af[mi], bf[ni]);
        }
    }

#pragma unroll
    for (int mi = 0; mi < 4; mi++) {
        int r0 = bm + wm + mi * 16 + g;
#pragma unroll
        for (int ni = 0; ni < 4; ni++) {
            int cb = bn + wn + ni * 8 + 2 * t;
            float b0 = bias[cb], b1 = bias[cb + 1];
            float x00 = (acc[mi][ni][0] + b0) * scale;
            float x01 = (acc[mi][ni][1] + b1) * scale;
            float x10 = (acc[mi][ni][2] + b0) * scale;
            float x11 = (acc[mi][ni][3] + b1) * scale;
            float2 v0, v1;
            if (conv) {
                v0 = make_float2(__uint_as_float(f2tf(x00)),
                                 __uint_as_float(f2tf(x01)));
                v1 = make_float2(__uint_as_float(f2tf(x10)),
                                 __uint_as_float(f2tf(x11)));
            } else {
                v0 = make_float2(x00, x01);
                v1 = make_float2(x10, x11);
            }
            *(float2*)&C[(size_t)r0 * N + cb]       = v0;
            *(float2*)&C[(size_t)(r0 + 8) * N + cb] = v1;
        }
    }
}

// ---------------------------------------------------------------------------
// Flash-attention. Block = (128-query tile, head, batch), 4 warps x 32 rows.
// Each B-fragment (K and V) is shared by TWO mmas (mi=0,1) -> 0.75 LDS/mma.
// Q tile in smem (stride 68: (4g+t) mod 32 conflict-free A-frag loads).
// K/V natural [key][d] layout stride 76: (12g+t)/(12t+g) conflict-free.
// cp.async double-buffered K/V tiles of 64 keys.
// ---------------------------------------------------------------------------
#define QROWS 128
#define KTILE 64
#define NT (SEQ / KTILE)
#define AT_S 76
#define QS_S 68
#define STAGE_FLOATS (KTILE * AT_S * 2 + 64)     // Ks + Vs + mask
#define QS_FLOATS (QROWS * QS_S)
#define ATTN_SMEM ((2 * STAGE_FLOATS + QS_FLOATS) * (int)sizeof(float))

__device__ __forceinline__ void attn_prefetch(
    float* stage, const unsigned* kb, const unsigned* vb, const int* mb, int tid)
{
    float* Ks = stage;
    float* Vs = stage + KTILE * AT_S;
    float* Mk = Vs + KTILE * AT_S;
#pragma unroll
    for (int j = 0; j < 8; j++) {
        int c = tid + j * 128;
        int r = c >> 4, col = (c & 15) << 2;
        cp_cg16(Ks + r * AT_S + col, kb + (size_t)r * DM + col);
        cp_cg16(Vs + r * AT_S + col, vb + (size_t)r * DM + col);
    }
    if (tid < 16) cp_cg16(Mk + tid * 4, mb + tid * 4);
}

__global__ __launch_bounds__(128) void attn_mma(
    const unsigned* __restrict__ qw, const unsigned* __restrict__ kw,
    const unsigned* __restrict__ vw, const int* __restrict__ vmask,
    unsigned* __restrict__ ctx)
{
    const int tid  = threadIdx.x;
    const int lane = tid & 31;
    const int warp = tid >> 5;
    const int g = lane >> 2, t = lane & 3;
    const int qrow0 = warp * 32;
    const int qt = blockIdx.x, h = blockIdx.y, b = blockIdx.z;

    float* Qs = sm_dyn + 2 * STAGE_FLOATS;
    const unsigned* Qu = (const unsigned*)Qs;

    // Stage Q tile (128 rows x 64 dims of tf32 bits, pre-scaled 1/8)
    const unsigned* qb = qw + ((size_t)b * SEQ + qt * QROWS) * DM + h * HD;
#pragma unroll
    for (int j = 0; j < 16; j++) {
        int c = tid + j * 128;
        int r = c >> 4, col = (c & 15) << 2;
        cp_cg16(Qs + r * QS_S + col, qb + (size_t)r * DM + col);
    }

    const unsigned* kbase = kw + ((size_t)b * SEQ) * DM + h * HD;
    const unsigned* vbase = vw + ((size_t)b * SEQ) * DM + h * HD;
    const int*      mbase = vmask + b * SEQ;

    attn_prefetch(sm_dyn, kbase, vbase, mbase, tid);
    asm volatile("cp.async.commit_group;" ::: "memory");

    float m[2][2], l[2][2];
#pragma unroll
    for (int mi = 0; mi < 2; mi++) {
        m[mi][0] = -1e30f; m[mi][1] = -1e30f;
        l[mi][0] = 0.0f;   l[mi][1] = 0.0f;
    }
    float o[2][8][4];
#pragma unroll
    for (int mi = 0; mi < 2; mi++)
#pragma unroll
        for (int nf = 0; nf < 8; nf++)
#pragma unroll
            for (int e = 0; e < 4; e++) o[mi][nf][e] = 0.0f;

    const int srcA = (lane & ~3) | (t >> 1);
    const int srcB = srcA + 2;
    const bool odd = (t & 1);

    for (int kt = 0; kt < NT; kt++) {
        const int st = kt & 1;
        asm volatile("cp.async.wait_group 0;" ::: "memory");
        __syncthreads();
        if (kt + 1 < NT) {
            attn_prefetch(sm_dyn + (st ^ 1) * STAGE_FLOATS,
                          kbase + (size_t)(kt + 1) * KTILE * DM,
                          vbase + (size_t)(kt + 1) * KTILE * DM,
                          mbase + (kt + 1) * KTILE, tid);
            asm volatile("cp.async.commit_group;" ::: "memory");
        }
        const unsigned* Ks = (const unsigned*)(sm_dyn + st * STAGE_FLOATS);
        const unsigned* Vs = Ks + KTILE * AT_S;
        const int*      Mk = (const int*)(Vs + KTILE * AT_S);

        // ---- S = Qs . K^T : B-frag shared across mi ----
        float s[2][8][4];
#pragma unroll
        for (int mi = 0; mi < 2; mi++)
#pragma unroll
            for (int nf = 0; nf < 8; nf++)
#pragma unroll
                for (int e = 0; e < 4; e++) s[mi][nf][e] = 0.0f;

#pragma unroll
        for (int kf = 0; kf < 8; kf++) {
            unsigned a0[4], a1[4];
            a0[0] = Qu[(qrow0 + g)      * QS_S + kf * 8 + t];
            a0[1] = Qu[(qrow0 + g + 8)  * QS_S + kf * 8 + t];
            a0[2] = Qu[(qrow0 + g)      * QS_S + kf * 8 + t + 4];
            a0[3] = Qu[(qrow0 + g + 8)  * QS_S + kf * 8 + t + 4];
            a1[0] = Qu[(qrow0 + g + 16) * QS_S + kf * 8 + t];
            a1[1] = Qu[(qrow0 + g + 24) * QS_S + kf * 8 + t];
            a1[2] = Qu[(qrow0 + g + 16) * QS_S + kf * 8 + t + 4];
            a1[3] = Qu[(qrow0 + g + 24) * QS_S + kf * 8 + t + 4];
#pragma unroll
            for (int nf = 0; nf < 8; nf++) {
                unsigned bfr[2];
                bfr[0] = Ks[(nf * 8 + g) * AT_S + kf * 8 + t];
                bfr[1] = Ks[(nf * 8 + g) * AT_S + kf * 8 + t + 4];
                mma_tf32(s[0][nf], a0, bfr);
                mma_tf32(s[1][nf], a1, bfr);
            }
        }

        // ---- mask + online softmax (per mi independent) ----
#pragma unroll
        for (int mi = 0; mi < 2; mi++) {
            float mx0 = -1e30f, mx1 = -1e30f;
#pragma unroll
            for (int nf = 0; nf < 8; nf++) {
                float pen0 = Mk[nf * 8 + 2 * t]     ? 0.0f : 1e12f;
                float pen1 = Mk[nf * 8 + 2 * t + 1] ? 0.0f : 1e12f;
                s[mi][nf][0] -= pen0; s[mi][nf][1] -= pen1;
                s[mi][nf][2] -= pen0; s[mi][nf][3] -= pen1;
                mx0 = fmaxf(mx0, fmaxf(s[mi][nf][0], s[mi][nf][1]));
                mx1 = fmaxf(mx1, fmaxf(s[mi][nf][2], s[mi][nf][3]));
            }
            mx0 = fmaxf(mx0, __shfl_xor_sync(0xffffffffu, mx0, 1));
            mx0 = fmaxf(mx0, __shfl_xor_sync(0xffffffffu, mx0, 2));
            mx1 = fmaxf(mx1, __shfl_xor_sync(0xffffffffu, mx1, 1));
            mx1 = fmaxf(mx1, __shfl_xor_sync(0xffffffffu, mx1, 2));
            float mn0 = fmaxf(m[mi][0], mx0), mn1 = fmaxf(m[mi][1], mx1);
            float al0 = __expf(m[mi][0] - mn0), al1 = __expf(m[mi][1] - mn1);
            m[mi][0] = mn0; m[mi][1] = mn1;
            float sum0 = 0.0f, sum1 = 0.0f;
#pragma unroll
            for (int nf = 0; nf < 8; nf++) {
                s[mi][nf][0] = __expf(s[mi][nf][0] - mn0);
                s[mi][nf][1] = __expf(s[mi][nf][1] - mn0);
                s[mi][nf][2] = __expf(s[mi][nf][2] - mn1);
                s[mi][nf][3] = __expf(s[mi][nf][3] - mn1);
                sum0 += s[mi][nf][0] + s[mi][nf][1];
                sum1 += s[mi][nf][2] + s[mi][nf][3];
            }
            sum0 += __shfl_xor_sync(0xffffffffu, sum0, 1);
            sum0 += __shfl_xor_sync(0xffffffffu, sum0, 2);
            sum1 += __shfl_xor_sync(0xffffffffu, sum1, 1);
            sum1 += __shfl_xor_sync(0xffffffffu, sum1, 2);
            l[mi][0] = l[mi][0] * al0 + sum0;
            l[mi][1] = l[mi][1] * al1 + sum1;
#pragma unroll
            for (int nf = 0; nf < 8; nf++) {
                o[mi][nf][0] *= al0; o[mi][nf][1] *= al0;
                o[mi][nf][2] *= al1; o[mi][nf][3] *= al1;
            }
        }

        // ---- O += P . V : V B-frag shared across mi ----
#pragma unroll
        for (int kf = 0; kf < 8; kf++) {
            unsigned af[2][4];
#pragma unroll
            for (int mi = 0; mi < 2; mi++) {
                float x0 = __shfl_sync(0xffffffffu, s[mi][kf][0], srcA);
                float x1 = __shfl_sync(0xffffffffu, s[mi][kf][1], srcA);
                float x2 = __shfl_sync(0xffffffffu, s[mi][kf][2], srcA);
                float x3 = __shfl_sync(0xffffffffu, s[mi][kf][3], srcA);
                float y0 = __shfl_sync(0xffffffffu, s[mi][kf][0], srcB);
                float y1 = __shfl_sync(0xffffffffu, s[mi][kf][1], srcB);
                float y2 = __shfl_sync(0xffffffffu, s[mi][kf][2], srcB);
                float y3 = __shfl_sync(0xffffffffu, s[mi][kf][3], srcB);
                af[mi][0] = f2tf(odd ? x1 : x0);
                af[mi][1] = f2tf(odd ? x3 : x2);
                af[mi][2] = f2tf(odd ? y1 : y0);
                af[mi][3] = f2tf(odd ? y3 : y2);
            }
#pragma unroll
            for (int nf = 0; nf < 8; nf++) {
                unsigned bfr[2];
                bfr[0] = Vs[(kf * 8 + t)     * AT_S + nf * 8 + g];
                bfr[1] = Vs[(kf * 8 + t + 4) * AT_S + nf * 8 + g];
                mma_tf32(o[0][nf], af[0], bfr);
                mma_tf32(o[1][nf], af[1], bfr);
            }
        }
    }

    // ---- normalize; write ctx as tf32 bits ----
    unsigned* obase = ctx + ((size_t)b * SEQ + qt * QROWS + qrow0) * DM + h * HD;
#pragma unroll
    for (int mi = 0; mi < 2; mi++) {
        float inv0 = 1.0f / l[mi][0], inv1 = 1.0f / l[mi][1];
        unsigned* ob = obase + (size_t)(mi * 16) * DM;
#pragma unroll
        for (int nf = 0; nf < 8; nf++) {
            int col = nf * 8 + 2 * t;
            uint2 v0, v1;
            v0.x = f2tf(o[mi][nf][0] * inv0);
            v0.y = f2tf(o[mi][nf][1] * inv0);
            v1.x = f2tf(o[mi][nf][2] * inv1);
            v1.y = f2tf(o[mi][nf][3] * inv1);
            *(uint2*)&ob[(size_t)g * DM + col]       = v0;
            *(uint2*)&ob[(size_t)(g + 8) * DM + col] = v1;
        }
    }
}

// ---------------------------------------------------------------------------
extern "C" void kernel_launch(void* const* d_in, const int* in_sizes, int n_in,
                              void* d_out, int out_size)
{
    const float* q    = (const float*)d_in[0];
    const float* k    = (const float*)d_in[1];
    const float* v    = (const float*)d_in[2];
    const int*   mask = (const int*)  d_in[3];
    const float* Wq   = (const float*)d_in[4];
    const float* bq   = (const float*)d_in[5];
    const float* Wk   = (const float*)d_in[6];
    const float* bk   = (const float*)d_in[7];
    const float* Wv   = (const float*)d_in[8];
    const float* bv   = (const float*)d_in[9];
    const float* Wo   = (const float*)d_in[10];
    const float* bo   = (const float*)d_in[11];
    float* out = (float*)d_out;

    void *pqt, *pkt, *pvt, *pw4, *pqw, *pkw, *pvw, *pctx;
    cudaGetSymbolAddress(&pqt, g_qt);
    cudaGetSymbolAddress(&pkt, g_kt);
    cudaGetSymbolAddress(&pvt, g_vt);
    cudaGetSymbolAddress(&pw4, g_w4);
    cudaGetSymbolAddress(&pqw, g_qw);
    cudaGetSymbolAddress(&pkw, g_kw);
    cudaGetSymbolAddress(&pvw, g_vw);
    cudaGetSymbolAddress(&pctx, g_ctx);

    unsigned* qt  = (unsigned*)pqt;
    unsigned* kt  = (unsigned*)pkt;
    unsigned* vt  = (unsigned*)pvt;
    unsigned* w4  = (unsigned*)pw4;
    unsigned* qwp = (unsigned*)pqw;
    unsigned* kwp = (unsigned*)pkw;
    unsigned* vwp = (unsigned*)pvw;
    unsigned* ctx = (unsigned*)pctx;

    static int attr_set = 0;
    cudaFuncSetAttribute(gemm_tf32,
                         cudaFuncAttributeMaxDynamicSharedMemorySize, GEMM_SMEM);
    cudaFuncSetAttribute(attn_mma,
                         cudaFuncAttributeMaxDynamicSharedMemorySize, ATTN_SMEM);
    (void)attr_set;

    // 1) one-shot tf32 conversions
    const int nBig = MROWS * DM / 4, nW = DM * DM / 4;
    to_tf32_k<<<nBig / 256, 256>>>((const float4*)q, (uint4*)qt, nBig);
    to_tf32_k<<<nBig / 256, 256>>>((const float4*)k, (uint4*)kt, nBig);
    to_tf32_k<<<nBig / 256, 256>>>((const float4*)v, (uint4*)vt, nBig);
    to_tf32_k<<<nW / 256, 256>>>((const float4*)Wq, (uint4*)(w4 + 0 * DM * DM), nW);
    to_tf32_k<<<nW / 256, 256>>>((const float4*)Wk, (uint4*)(w4 + 1 * DM * DM), nW);
    to_tf32_k<<<nW / 256, 256>>>((const float4*)Wv, (uint4*)(w4 + 2 * DM * DM), nW);
    to_tf32_k<<<nW / 256, 256>>>((const float4*)Wo, (uint4*)(w4 + 3 * DM * DM), nW);

    dim3 ggrid(DM / 128, MROWS / 128);   // (8, 32)

    // 2) projections -> tf32 bits (Q pre-scaled by 1/sqrt(64))
    gemm_tf32<<<ggrid, 256, GEMM_SMEM>>>(qt, w4 + 0 * DM * DM, bq,
                                         (float*)qwp, MROWS, DM, DM, 0.125f, 1);
    gemm_tf32<<<ggrid, 256, GEMM_SMEM>>>(kt, w4 + 1 * DM * DM, bk,
                                         (float*)kwp, MROWS, DM, DM, 1.0f, 1);
    gemm_tf32<<<ggrid, 256, GEMM_SMEM>>>(vt, w4 + 2 * DM * DM, bv,
                                         (float*)vwp, MROWS, DM, DM, 1.0f, 1);

    // 3) fused attention -> ctx (tf32 bits)
    attn_mma<<<dim3(SEQ / QROWS, NH, NB), 128, ATTN_SMEM>>>(
        qwp, kwp, vwp, mask, ctx);

    // 4) output projection (fp32 out)
    gemm_tf32<<<ggrid, 256, GEMM_SMEM>>>(ctx, w4 + 3 * DM * DM, bo,
                                         out, MROWS, DM, DM, 1.0f, 0);
}